// round 16
// baseline (speedup 1.0000x reference)
#include <cuda_runtime.h>
#include <cuda_fp16.h>
#include <cstdint>

#define HID      512
#define NOBJ     8192
#define NREL     32768
#define POOL     4096
#define NRELCLS  51
#define NOBJCLS  151

// -------------------- device scratch --------------------
__device__ __align__(256) __half g_edge_hi[NOBJ * 1024];
__device__ __align__(256) __half g_wcatT[POOL * 1024];   // [n][k] fp16
__device__ __align__(256) __half g_wctxT[64 * POOL];     // [cls pad64][k] fp16
__device__ __align__(256) __half g_ec_hi[NOBJ * HID];    // edge_ctx fp16
__device__ __align__(256) __half g_wembT[1024 * HID];    // [n][k] fp16
__device__ __align__(256) __half g_U[NOBJ * POOL];       // head_rep @ Wcat_top
__device__ __align__(256) __half g_V[NOBJ * POOL];       // tail_rep @ Wcat_bot + bcat

// -------------------- helpers --------------------
__device__ __forceinline__ uint32_t smem_u32(const void* p) {
    uint32_t a;
    asm("{ .reg .u64 t; cvta.to.shared.u64 t, %1; cvt.u32.u64 %0, t; }" : "=r"(a) : "l"(p));
    return a;
}
#define CP16(d, s)   asm volatile("cp.async.cg.shared.global [%0], [%1], 16;" :: "r"(d), "l"(s) : "memory")
#define CP_COMMIT()  asm volatile("cp.async.commit_group;" ::: "memory")
#define WAITG(n)     asm volatile("cp.async.wait_group %0;" :: "n"(n) : "memory")

__device__ __forceinline__ void ldsm4(uint32_t* r, uint32_t a) {
    asm volatile("ldmatrix.sync.aligned.m8n8.x4.shared.b16 {%0,%1,%2,%3}, [%4];"
                 : "=r"(r[0]), "=r"(r[1]), "=r"(r[2]), "=r"(r[3]) : "r"(a));
}
__device__ __forceinline__ void mma16816(float* d, const uint32_t* a, uint32_t b0, uint32_t b1) {
    asm volatile(
        "mma.sync.aligned.m16n8k16.row.col.f32.f16.f16.f32 "
        "{%0,%1,%2,%3}, {%4,%5,%6,%7}, {%8,%9}, {%0,%1,%2,%3};"
        : "+f"(d[0]), "+f"(d[1]), "+f"(d[2]), "+f"(d[3])
        : "r"(a[0]), "r"(a[1]), "r"(a[2]), "r"(a[3]), "r"(b0), "r"(b1));
}
__device__ __forceinline__ uint32_t packh(float e0, float e1) {
    uint32_t r;
    asm("cvt.rn.f16x2.f32 %0, %1, %2;" : "=r"(r) : "f"(e1), "f"(e0));  // low = e0
    return r;
}

// -------------------- smem layouts --------------------
#define GSTAGE   32768           // A [128m][64k] 16KB + B [128n][64k] 16KB
#define G_A      0
#define G_B      16384
#define SMEM_G   65536           // 64KB -> 2 CTAs/SM

#define ZP_Z     0               // 2 subs of z [64m][64k] fp16 = 16KB
#define ZP_WC    16384           // 2 subs of Wctx [64cls][64k] = 16KB
#define ZP_P0    32768
#define ZP_P1    33024
#define ZP_OP    33280
#define SMEM_ZP  33792           // 33KB -> 4 CTAs/SM (regs permitting)

// ===========================================================================
// Merged prep kernel: blockIdx.x ranges select task.
//   [0, 16384)            : ec_prep (linear, 4M elems)
//   [16384, 16896)        : wemb transpose (grid 32 x 16)
//   [16896, 20992)        : wcat transpose (grid 128 x 32)
//   [20992, 22016)        : wctx (linear, 256K elems)
// 256 threads each.
// ===========================================================================
__global__ void k_prep(const float* __restrict__ edge_ctx,
                       const float* __restrict__ wemb,
                       const float* __restrict__ wcat,
                       const float* __restrict__ wctx)
{
    __shared__ float tile[32][33];
    const int b = blockIdx.x;
    const int t = threadIdx.x;
    const int tx = t & 31, ty = t >> 5;

    if (b < 16384) {                       // ec_prep
        int idx = b * 256 + t;
        g_ec_hi[idx] = __float2half_rn(edge_ctx[idx]);
    } else if (b < 16896) {                // wemb: [512][1024] -> [1024][512]
        int bi = b - 16384;
        int c0 = (bi & 31) * 32, r0 = (bi >> 5) * 32;
        for (int i = ty; i < 32; i += 8)
            tile[i][tx] = wemb[(size_t)(r0 + i) * 1024 + c0 + tx];
        __syncthreads();
        for (int i = ty; i < 32; i += 8)
            g_wembT[(size_t)(c0 + i) * HID + r0 + tx] = __float2half_rn(tile[tx][i]);
    } else if (b < 20992) {                // wcat: [1024][4096] -> [4096][1024]
        int bi = b - 16896;
        int c0 = (bi & 127) * 32, r0 = (bi >> 7) * 32;
        for (int i = ty; i < 32; i += 8)
            tile[i][tx] = wcat[(size_t)(r0 + i) * POOL + c0 + tx];
        __syncthreads();
        for (int i = ty; i < 32; i += 8)
            g_wcatT[(size_t)(c0 + i) * 1024 + r0 + tx] = __float2half_rn(tile[tx][i]);
    } else {                               // wctx pad64 transpose
        int idx = (b - 20992) * 256 + t;
        int c = idx >> 12, k = idx & 4095;
        float v = (c < NRELCLS) ? wctx[(size_t)k * NRELCLS + c] : 0.f;
        g_wctxT[idx] = __float2half_rn(v);
    }
}

// ===========================================================================
// GEMM1 (2 CTAs/SM): edge_rep = relu(edge_ctx @ W_post_emb + b) -> fp16
// 256 threads, CTA tile M128 x N128, warp grid 4m x 2n (tile 32x64).
// ===========================================================================
__global__ __launch_bounds__(256, 2) void k_gemm1_mma(const float* __restrict__ bias)
{
    extern __shared__ __align__(1024) char smc[];
    const uint32_t sb = smem_u32(smc);
    const int t = threadIdx.x;
    const int lane = t & 31, wid = t >> 5;
    const int wm = wid >> 1, wn = wid & 1;
    const int m0 = blockIdx.x * 128, n0 = blockIdx.y * 128;

    auto load_stage = [&](int kc) {
        const uint32_t base = sb + (kc & 1) * GSTAGE;
#pragma unroll
        for (int i = 0; i < 4; i++) {
            int idx = t + i * 256;
            int row = idx >> 3, j = idx & 7;
            uint32_t d = (uint32_t)row * 128 + (((uint32_t)j * 16) ^ ((uint32_t)(row & 7) << 4));
            CP16(base + G_A + d, &g_ec_hi[(size_t)(m0 + row) * HID + kc * 64 + j * 8]);
            CP16(base + G_B + d, &g_wembT[(size_t)(n0 + row) * HID + kc * 64 + j * 8]);
        }
    };
    load_stage(0); CP_COMMIT();
    load_stage(1); CP_COMMIT();

    const uint32_t xorv = (lane & 7) << 4;
    const uint32_t khb  = (lane >> 4) * 16;
    const uint32_t arow = (uint32_t)(wm * 32 + (lane & 15)) * 128;
    const uint32_t brow = (uint32_t)(wn * 64 + (lane & 15)) * 128;

    float acc[2][8][4];
#pragma unroll
    for (int a = 0; a < 2; a++)
#pragma unroll
        for (int b = 0; b < 8; b++)
#pragma unroll
            for (int c = 0; c < 4; c++) acc[a][b][c] = 0.f;

    for (int kc = 0; kc < 8; kc++) {
        if (kc == 7) { WAITG(0); } else { WAITG(1); }
        __syncthreads();
        const uint32_t base = sb + (kc & 1) * GSTAGE;
#pragma unroll
        for (int ks = 0; ks < 4; ks++) {
            const uint32_t col = (uint32_t)(ks * 32 + khb) ^ xorv;
            uint32_t bf[4][4];
#pragma unroll
            for (int q = 0; q < 4; q++)
                ldsm4(bf[q], base + G_B + brow + q * 16 * 128 + col);
            uint32_t ah[2][4];
#pragma unroll
            for (int mt = 0; mt < 2; mt++)
                ldsm4(ah[mt], base + G_A + arow + mt * 16 * 128 + col);
#pragma unroll
            for (int mt = 0; mt < 2; mt++)
#pragma unroll
                for (int nt = 0; nt < 8; nt++)
                    mma16816(acc[mt][nt], ah[mt],
                             bf[nt >> 1][nt & 1], bf[nt >> 1][2 + (nt & 1)]);
        }
        __syncthreads();
        if (kc + 2 < 8) { load_stage(kc + 2); CP_COMMIT(); }
    }

#pragma unroll
    for (int mt = 0; mt < 2; mt++) {
        const int row = m0 + wm * 32 + mt * 16 + (lane >> 2);
#pragma unroll
        for (int nt = 0; nt < 8; nt++) {
            const int col = n0 + wn * 64 + nt * 8 + (lane & 3) * 2;
            float2 bb = *(const float2*)&bias[col];
            *(uint32_t*)&g_edge_hi[(size_t)row * 1024 + col] =
                packh(fmaxf(acc[mt][nt][0] + bb.x, 0.f), fmaxf(acc[mt][nt][1] + bb.y, 0.f));
            *(uint32_t*)&g_edge_hi[(size_t)(row + 8) * 1024 + col] =
                packh(fmaxf(acc[mt][nt][2] + bb.x, 0.f), fmaxf(acc[mt][nt][3] + bb.y, 0.f));
        }
    }
}

// ===========================================================================
// UV GEMM (2 CTAs/SM): U = head_rep @ Wcat_top, V = tail_rep @ Wcat_bot (+bcat)
// ===========================================================================
__global__ __launch_bounds__(256, 2) void k_uv(const float* __restrict__ bcat)
{
    extern __shared__ __align__(1024) char smc[];
    const uint32_t sb = smem_u32(smc);
    const int t = threadIdx.x;
    const int lane = t & 31, wid = t >> 5;
    const int wm = wid >> 1, wn = wid & 1;
    const int m0 = blockIdx.x * 128, n0 = blockIdx.y * 128;
    const int zsel = blockIdx.z;
    const int koff = zsel * 512;
    __half* dst = zsel ? g_V : g_U;

    auto load_stage = [&](int kc) {
        const uint32_t base = sb + (kc & 1) * GSTAGE;
#pragma unroll
        for (int i = 0; i < 4; i++) {
            int idx = t + i * 256;
            int row = idx >> 3, j = idx & 7;
            uint32_t d = (uint32_t)row * 128 + (((uint32_t)j * 16) ^ ((uint32_t)(row & 7) << 4));
            CP16(base + G_A + d, &g_edge_hi[(size_t)(m0 + row) * 1024 + koff + kc * 64 + j * 8]);
            CP16(base + G_B + d, &g_wcatT[(size_t)(n0 + row) * 1024 + koff + kc * 64 + j * 8]);
        }
    };
    load_stage(0); CP_COMMIT();
    load_stage(1); CP_COMMIT();

    const uint32_t xorv = (lane & 7) << 4;
    const uint32_t khb  = (lane >> 4) * 16;
    const uint32_t arow = (uint32_t)(wm * 32 + (lane & 15)) * 128;
    const uint32_t brow = (uint32_t)(wn * 64 + (lane & 15)) * 128;

    float acc[2][8][4];
#pragma unroll
    for (int a = 0; a < 2; a++)
#pragma unroll
        for (int b = 0; b < 8; b++)
#pragma unroll
            for (int c = 0; c < 4; c++) acc[a][b][c] = 0.f;

    for (int kc = 0; kc < 8; kc++) {
        if (kc == 7) { WAITG(0); } else { WAITG(1); }
        __syncthreads();
        const uint32_t base = sb + (kc & 1) * GSTAGE;
#pragma unroll
        for (int ks = 0; ks < 4; ks++) {
            const uint32_t col = (uint32_t)(ks * 32 + khb) ^ xorv;
            uint32_t bf[4][4];
#pragma unroll
            for (int q = 0; q < 4; q++)
                ldsm4(bf[q], base + G_B + brow + q * 16 * 128 + col);
            uint32_t ah[2][4];
#pragma unroll
            for (int mt = 0; mt < 2; mt++)
                ldsm4(ah[mt], base + G_A + arow + mt * 16 * 128 + col);
#pragma unroll
            for (int mt = 0; mt < 2; mt++)
#pragma unroll
                for (int nt = 0; nt < 8; nt++)
                    mma16816(acc[mt][nt], ah[mt],
                             bf[nt >> 1][nt & 1], bf[nt >> 1][2 + (nt & 1)]);
        }
        __syncthreads();
        if (kc + 2 < 8) { load_stage(kc + 2); CP_COMMIT(); }
    }

    const float zf = zsel ? 1.f : 0.f;   // fold bcat into V only
#pragma unroll
    for (int mt = 0; mt < 2; mt++) {
        const int mloc = wm * 32 + mt * 16 + (lane >> 2);
#pragma unroll
        for (int nt = 0; nt < 8; nt++) {
            const int nl = n0 + wn * 64 + nt * 8 + (lane & 3) * 2;
            float2 bb = *(const float2*)&bcat[nl];
            float bx = bb.x * zf, by = bb.y * zf;
            *(uint32_t*)&dst[(size_t)(m0 + mloc) * POOL + nl] =
                packh(acc[mt][nt][0] + bx, acc[mt][nt][1] + by);
            *(uint32_t*)&dst[(size_t)(m0 + mloc + 8) * POOL + nl] =
                packh(acc[mt][nt][2] + bx, acc[mt][nt][3] + by);
        }
    }
}

// ===========================================================================
// z-pass (M=64, 128 threads, 4 CTAs/SM): z = (U[p0]+V'[p1])*union -> GEMM3
// Same structure as proven R12/R14 form, M extent halved.
// ===========================================================================
__global__ __launch_bounds__(128, 4) void k_zpass(
    const float* __restrict__ unionf,
    const int*   __restrict__ pairs,
    const int*   __restrict__ obj_preds,
    const float* __restrict__ bctx,
    const float* __restrict__ freq,
    float*       __restrict__ out)
{
    extern __shared__ __align__(1024) char smc[];
    const uint32_t sb = smem_u32(smc);
    const int t = threadIdx.x;
    const int lane = t & 31, wid = t >> 5;
    const int gm = wid >> 1, gn = wid & 1;     // 2m x 2n warps (32m x 32cls)
    const int r0 = blockIdx.x * 64;

    int* p0s = (int*)(smc + ZP_P0);
    int* p1s = (int*)(smc + ZP_P1);
    int* opx = (int*)(smc + ZP_OP);

    if (t < 64) {
        int a = pairs[(size_t)(r0 + t) * 2 + 0];
        int b = pairs[(size_t)(r0 + t) * 2 + 1];
        p0s[t] = a; p1s[t] = b;
        opx[t] = obj_preds[a] * NOBJCLS + obj_preds[b];
    }
    __syncthreads();

    const int m = t >> 1;                  // 0..63
    const int coff = (t & 1) * 64;
    const int sub = t & 1;
    const uint32_t xorm = (uint32_t)(m & 7) << 4;
    const __half* Ubase = &g_U[(size_t)p0s[m] * POOL];
    const __half* Vbase = &g_V[(size_t)p1s[m] * POOL];
    const float*  ubase = &unionf[(size_t)(r0 + m) * POOL];

    const uint32_t xorv = (lane & 7) << 4;
    const uint32_t khb  = (lane >> 4) * 16;
    const uint32_t zrow = (uint32_t)(gm * 32 + (lane & 15)) * 128;
    const uint32_t wrow = (uint32_t)(gn * 32 + (lane & 15)) * 128;

    float acc3[2][4][4];
#pragma unroll
    for (int a = 0; a < 2; a++)
#pragma unroll
        for (int b = 0; b < 4; b++)
#pragma unroll
            for (int c = 0; c < 4; c++) acc3[a][b][c] = 0.f;

    for (int nc = 0; nc < 32; nc++) {
        const int n0 = nc * 128;

        // W_ctx tiles: 2 subs of [64cls][64k] via cp.async (1024 slots, 128 thr)
#pragma unroll
        for (int i = 0; i < 8; i++) {
            int idx = t + i * 128;
            int s = idx >> 9, rem = idx & 511, row = rem >> 3, j = rem & 7;
            uint32_t d = (uint32_t)(ZP_WC + s * 8192) + (uint32_t)row * 128 +
                         (((uint32_t)j * 16) ^ ((uint32_t)(row & 7) << 4));
            CP16(sb + d, &g_wctxT[(size_t)row * POOL + n0 + s * 64 + j * 8]);
        }
        CP_COMMIT();

        // elementwise: 64 cols per thread (bcat pre-folded into V)
        {
            const uint4*  Up = (const uint4*)(Ubase + n0 + coff);
            const uint4*  Vp = (const uint4*)(Vbase + n0 + coff);
            const float4* up = (const float4*)(ubase + n0 + coff);
#pragma unroll
            for (int j = 0; j < 8; j++) {
                uint4 Uv = Up[j], Vv = Vp[j];
                float4 u0 = up[2 * j], u1 = up[2 * j + 1];
                const __half2* pu = (const __half2*)&Uv;
                const __half2* pv = (const __half2*)&Vv;
                float2 f0 = __half22float2(pu[0]), g0 = __half22float2(pv[0]);
                float2 f1 = __half22float2(pu[1]), g1 = __half22float2(pv[1]);
                float2 f2 = __half22float2(pu[2]), g2 = __half22float2(pv[2]);
                float2 f3 = __half22float2(pu[3]), g3 = __half22float2(pv[3]);
                uint4 o;
                o.x = packh((f0.x + g0.x) * u0.x, (f0.y + g0.y) * u0.y);
                o.y = packh((f1.x + g1.x) * u0.z, (f1.y + g1.y) * u0.w);
                o.z = packh((f2.x + g2.x) * u1.x, (f2.y + g2.y) * u1.y);
                o.w = packh((f3.x + g3.x) * u1.z, (f3.y + g3.y) * u1.w);
                *(uint4*)(smc + ZP_Z + sub * 8192 + (uint32_t)m * 128 +
                          (((uint32_t)j * 16) ^ xorm)) = o;
            }
        }
        WAITG(0);
        __syncthreads();

        // GEMM3: acc3 += z[64][128k] x Wctx[64cls][128k]
#pragma unroll
        for (int s = 0; s < 2; s++) {
#pragma unroll
            for (int ks = 0; ks < 4; ks++) {
                const uint32_t col = (uint32_t)(ks * 32 + khb) ^ xorv;
                uint32_t bf[2][4];
                ldsm4(bf[0], sb + ZP_WC + s * 8192 + wrow + col);
                ldsm4(bf[1], sb + ZP_WC + s * 8192 + wrow + 16 * 128 + col);
                uint32_t zfr[2][4];
#pragma unroll
                for (int mt = 0; mt < 2; mt++)
                    ldsm4(zfr[mt], sb + ZP_Z + s * 8192 + zrow + mt * 16 * 128 + col);
#pragma unroll
                for (int mt = 0; mt < 2; mt++)
#pragma unroll
                    for (int nt = 0; nt < 4; nt++)
                        mma16816(acc3[mt][nt], zfr[mt],
                                 bf[nt >> 1][nt & 1], bf[nt >> 1][2 + (nt & 1)]);
            }
        }
        __syncthreads();
    }

    // ---------------- final: out = acc3 + bctx + freq ----------------
#pragma unroll
    for (int mt = 0; mt < 2; mt++) {
        const int m0l = gm * 32 + mt * 16 + (lane >> 2);
#pragma unroll
        for (int r = 0; r < 2; r++) {
            const int mm = m0l + r * 8;
            const int pidx = opx[mm];
            const float* fr = &freq[(size_t)pidx * NRELCLS];
            float* op = &out[(size_t)(r0 + mm) * NRELCLS];
#pragma unroll
            for (int nt = 0; nt < 4; nt++) {
                const int c = gn * 32 + nt * 8 + (lane & 3) * 2;
                if (c < NRELCLS)
                    op[c] = acc3[mt][nt][r * 2 + 0] + bctx[c] + fr[c];
                if (c + 1 < NRELCLS)
                    op[c + 1] = acc3[mt][nt][r * 2 + 1] + bctx[c + 1] + fr[c + 1];
            }
        }
    }
}

// ===========================================================================
extern "C" void kernel_launch(void* const* d_in, const int* in_sizes, int n_in,
                              void* d_out, int out_size)
{
    const float* edge_ctx   = (const float*)d_in[0];
    const float* unionf     = (const float*)d_in[1];
    const int*   pairs      = (const int*)  d_in[2];
    const int*   obj_preds  = (const int*)  d_in[3];
    const float* W_post_emb = (const float*)d_in[4];
    const float* b_post_emb = (const float*)d_in[5];
    const float* W_post_cat = (const float*)d_in[6];
    const float* b_post_cat = (const float*)d_in[7];
    const float* W_ctx      = (const float*)d_in[8];
    const float* b_ctx      = (const float*)d_in[9];
    const float* freq       = (const float*)d_in[10];
    float* out = (float*)d_out;

    cudaFuncSetAttribute(k_gemm1_mma, cudaFuncAttributeMaxDynamicSharedMemorySize, SMEM_G);
    cudaFuncSetAttribute(k_uv,        cudaFuncAttributeMaxDynamicSharedMemorySize, SMEM_G);
    cudaFuncSetAttribute(k_zpass,     cudaFuncAttributeMaxDynamicSharedMemorySize, SMEM_ZP);

    k_prep<<<22016, 256>>>(edge_ctx, W_post_emb, W_post_cat, W_ctx);
    k_gemm1_mma<<<dim3(NOBJ / 128, 1024 / 128), 256, SMEM_G>>>(b_post_emb);
    k_uv<<<dim3(NOBJ / 128, POOL / 128, 2), 256, SMEM_G>>>(b_post_cat);
    k_zpass<<<NREL / 64, 128, SMEM_ZP>>>(unionf, pairs, obj_preds,
                                         b_ctx, freq, out);
}